// round 10
// baseline (speedup 1.0000x reference)
#include <cuda_runtime.h>
#include <cuda_fp16.h>
#include <math.h>
#include <stdint.h>

// Problem constants
#define Bb 4
#define Ll 4096
#define Hh 1024
#define Nn 16
#define NG 8            // state pairs (f32x2 groups)
#define Pc 32           // elements per scan thread
#define EPSV 1e-6f

typedef unsigned long long ull;

// ---------------- scratch (static device globals; no allocation) ----------------
__device__ float  g_u  [(size_t)Bb*Hh*Ll];   // normalized, masked, (B,H,L)  64MB
__device__ float2 g_lam  [Hh*Nn];
__device__ float2 g_cd2  [Hh*Nn];
__device__ float2 g_lamPk[6 * Hh * Nn];      // lamP^(2^k), k=0..5   (lamP = lam^32)
__device__ float2 g_lamPw[Hh * 32 * Nn];     // lamP^(lane+1)        4MB
__device__ __half g_wf16[2048u*1024u];            // W fp16 [o][k]      4MB
__device__ __half g_yf16[(size_t)1024u*16384u];   // Y fp16 [k=h][n]   32MB

// ================= PTX helpers (legal on base compute_103) =================
__device__ __forceinline__ uint32_t smem_u32(const void* p) {
    uint32_t a;
    asm("{ .reg .u64 t; cvta.to.shared.u64 t, %1; cvt.u32.u64 %0, t; }" : "=r"(a) : "l"(p));
    return a;
}
__device__ __forceinline__ void cp16(uint32_t dst, const void* src) {
    asm volatile("cp.async.cg.shared.global [%0], [%1], 16;" :: "r"(dst), "l"(src));
}
__device__ __forceinline__ void cp_commit() { asm volatile("cp.async.commit_group;"); }
__device__ __forceinline__ void cp_wait2()  { asm volatile("cp.async.wait_group 2;"); }
__device__ __forceinline__ void ldsm4(uint32_t* r, uint32_t addr) {
    asm volatile("ldmatrix.sync.aligned.m8n8.x4.shared.b16 {%0,%1,%2,%3}, [%4];"
                 : "=r"(r[0]), "=r"(r[1]), "=r"(r[2]), "=r"(r[3]) : "r"(addr));
}
__device__ __forceinline__ void ldsm4t(uint32_t* r, uint32_t addr) {
    asm volatile("ldmatrix.sync.aligned.m8n8.x4.trans.shared.b16 {%0,%1,%2,%3}, [%4];"
                 : "=r"(r[0]), "=r"(r[1]), "=r"(r[2]), "=r"(r[3]) : "r"(addr));
}
__device__ __forceinline__ void mma16816(float* d, const uint32_t* a, const uint32_t* b) {
    asm volatile("mma.sync.aligned.m16n8k16.row.col.f32.f16.f16.f32 "
                 "{%0,%1,%2,%3}, {%4,%5,%6,%7}, {%8,%9}, {%0,%1,%2,%3};"
                 : "+f"(d[0]), "+f"(d[1]), "+f"(d[2]), "+f"(d[3])
                 : "r"(a[0]), "r"(a[1]), "r"(a[2]), "r"(a[3]), "r"(b[0]), "r"(b[1]));
}
// ---- packed fp32x2 (Blackwell dual-FMA) ----
__device__ __forceinline__ ull pk2(float a, float b) {
    ull r; asm("mov.b64 %0, {%1,%2};" : "=l"(r) : "f"(a), "f"(b)); return r;
}
__device__ __forceinline__ void upk2(float& a, float& b, ull v) {
    asm("mov.b64 {%0,%1}, %2;" : "=f"(a), "=f"(b) : "l"(v));
}
__device__ __forceinline__ ull fma2(ull a, ull b, ull c) {
    ull d; asm("fma.rn.f32x2 %0, %1, %2, %3;" : "=l"(d) : "l"(a), "l"(b), "l"(c)); return d;
}
__device__ __forceinline__ ull mul2(ull a, ull b) {
    ull d; asm("mul.rn.f32x2 %0, %1, %2;" : "=l"(d) : "l"(a), "l"(b)); return d;
}

// ---------------- kernel 0: constants (double) + power tables + W fp32->fp16 -------
__global__ void fused_pre_kernel(const float* __restrict__ log_dt,
                                 const float* __restrict__ log_A_real,
                                 const float* __restrict__ A_imag,
                                 const float* __restrict__ C_real,
                                 const float* __restrict__ C_imag,
                                 const float* __restrict__ wmat) {
    unsigned int bid = blockIdx.x;
    if (bid < 8192u) {
        unsigned int i = bid * 256 + threadIdx.x;
        g_wf16[i] = __float2half_rn(wmat[i]);
        return;
    }
    int idx = (int)(bid - 8192u) * 256 + threadIdx.x;
    if (idx >= Hh * Nn) return;
    int h = idx / Nn;
    int n = idx - h * Nn;
    double dt  = exp((double)log_dt[h]);
    double Are = -exp((double)log_A_real[idx]);
    double Aim = (double)A_imag[idx];
    double dre = Are * dt, dim = Aim * dt;
    double er  = exp(dre);
    double lr  = er * cos(dim), li = er * sin(dim);
    g_lam[idx] = make_float2((float)lr, (float)li);
    // lamP = lam^32
    double magP = dre * (double)Pc;   // log-magnitude of lamP
    double angP = dim * (double)Pc;   // angle of lamP
    // powers lamP^(2^k), k=0..5
#pragma unroll
    for (int k = 0; k < 6; k++) {
        double pw = (double)(1 << k);
        g_lamPk[k * (Hh * Nn) + idx] =
            make_float2((float)(exp(magP * pw) * cos(angP * pw)),
                        (float)(exp(magP * pw) * sin(angP * pw)));
    }
    // powers lamP^(j+1), j=0..31
    for (int j = 0; j < 32; j++) {
        double pw = (double)(j + 1);
        g_lamPw[((size_t)h * 32 + j) * Nn + n] =
            make_float2((float)(exp(magP * pw) * cos(angP * pw)),
                        (float)(exp(magP * pw) * sin(angP * pw)));
    }
    // Cd = C*(lam-1)/A ; store 2*Cd
    double e1r = lr - 1.0, e1i = li;
    double Cr = (double)C_real[idx], Ci = (double)C_imag[idx];
    double nr = Cr * e1r - Ci * e1i;
    double ni = Cr * e1i + Ci * e1r;
    double den = Are * Are + Aim * Aim;
    double cdr = (nr * Are + ni * Aim) / den;
    double cdi = (ni * Are - nr * Aim) / den;
    g_cd2[idx] = make_float2((float)(2.0 * cdr), (float)(2.0 * cdi));
}

// ---------------- kernel 1: fused RMSNorm + mask + transpose ----------------
#define NF_TILE  (32 * 1025)
#define NF_SMEM  ((NF_TILE + 32 + 1024) * 4)
__global__ __launch_bounds__(256) void norm_fused_kernel(const float* __restrict__ hs,
                                                         const float* __restrict__ mask,
                                                         const float* __restrict__ w) {
    extern __shared__ float sm[];
    float* tile = sm;
    float* rm   = sm + NF_TILE;
    float* w_s  = sm + NF_TILE + 32;
    int b  = blockIdx.y;
    int l0 = blockIdx.x * 32;
    int tid = threadIdx.x;
    int row = tid >> 3;
    int sub = tid & 7;

    for (int i = tid; i < 1024; i += 256) w_s[i] = w[i];

    const float4* src = (const float4*)(hs + ((size_t)(b * Ll + l0 + row)) * Hh);
    float ss = 0.f;
#pragma unroll
    for (int i = 0; i < 32; i++) {
        int col4 = i * 8 + sub;
        float4 v = src[col4];
        ss += v.x * v.x + v.y * v.y + v.z * v.z + v.w * v.w;
        float* dst = &tile[row * 1025 + col4 * 4];
        dst[0] = v.x; dst[1] = v.y; dst[2] = v.z; dst[3] = v.w;
    }
#pragma unroll
    for (int o = 4; o; o >>= 1) ss += __shfl_xor_sync(0xffffffffu, ss, o);
    if (sub == 0)
        rm[row] = rsqrtf(ss * (1.0f / Hh) + EPSV) * mask[b * Ll + l0 + row];
    __syncthreads();

#pragma unroll 8
    for (int i = 0; i < 128; i++) {
        int lin = i * 256 + tid;
        int h = lin >> 5, l = lin & 31;
        g_u[((size_t)(b * Hh + h)) * Ll + l0 + l] = tile[l * 1025 + h] * rm[l] * w_s[h];
    }
}

// ---------------- kernel 2: FUSED scan, f32x2, table-driven (low reg pressure) -----
__global__ __launch_bounds__(128) void scan_fused_kernel(const float* __restrict__ Dvec) {
    int bh  = blockIdx.x;
    int hh  = bh & (Hh - 1);
    int b   = bh >> 10;
    int tid = threadIdx.x;
    int lane = tid & 31, wrp = tid >> 5;

    ull SR[NG], SI[NG];
#pragma unroll
    for (int g = 0; g < NG; g++) { SR[g] = 0ull; SI[g] = 0ull; }

    const float4* up = (const float4*)(g_u + (size_t)bh * Ll + tid * Pc);

    // ---- phase 1: local scan of 32 elements (lam constants scoped/dead after) ----
    {
        ull LR[NG], LI[NG], NLI[NG];
#pragma unroll
        for (int g = 0; g < NG; g++) {
            float2 v0 = g_lam[hh * Nn + 2 * g];
            float2 v1 = g_lam[hh * Nn + 2 * g + 1];
            LR[g]  = pk2(v0.x, v1.x);
            LI[g]  = pk2(v0.y, v1.y);
            NLI[g] = pk2(-v0.y, -v1.y);
        }
#pragma unroll
        for (int q = 0; q < Pc / 4; q++) {
            float4 uv = up[q];
            float xs[4] = {uv.x, uv.y, uv.z, uv.w};
#pragma unroll
            for (int e = 0; e < 4; e++) {
                ull xx = pk2(xs[e], xs[e]);
#pragma unroll
                for (int g = 0; g < NG; g++) {
                    ull nr = fma2(LR[g], SR[g], fma2(NLI[g], SI[g], xx));
                    ull ni = fma2(LR[g], SI[g], mul2(LI[g], SR[g]));
                    SR[g] = nr; SI[g] = ni;
                }
            }
        }
    }

    // ---- phase 2: Kogge-Stone over 32 lanes; step multipliers from table ----
#pragma unroll
    for (int k = 0; k < 5; k++) {
        int off = 1 << k;
        const float2* mk = g_lamPk + k * (Hh * Nn) + hh * Nn;
#pragma unroll
        for (int g = 0; g < NG; g++) {
            float2 m0 = mk[2 * g], m1 = mk[2 * g + 1];
            ull MRg = pk2(m0.x, m1.x);
            ull MIg = pk2(m0.y, m1.y);
            ull NMIg = pk2(-m0.y, -m1.y);
            ull vr = __shfl_up_sync(0xffffffffu, SR[g], off);
            ull vi = __shfl_up_sync(0xffffffffu, SI[g], off);
            ull nsr = fma2(MRg, vr, fma2(NMIg, vi, SR[g]));
            ull nsi = fma2(MRg, vi, fma2(MIg, vr, SI[g]));
            if (lane >= off) { SR[g] = nsr; SI[g] = nsi; }
        }
    }

    // cross-warp combine with M32 = lamP^32
    __shared__ ull Swr[4][NG], Swi[4][NG];
    if (lane == 31) {
#pragma unroll
        for (int g = 0; g < NG; g++) { Swr[wrp][g] = SR[g]; Swi[wrp][g] = SI[g]; }
    }
    __syncthreads();
    {
        const float2* mk = g_lamPk + 5 * (Hh * Nn) + hh * Nn;
        const float2* pw = g_lamPw + ((size_t)hh * 32 + lane) * Nn;
#pragma unroll
        for (int g = 0; g < NG; g++) {
            float2 m0 = mk[2 * g], m1 = mk[2 * g + 1];
            ull MRg = pk2(m0.x, m1.x);
            ull MIg = pk2(m0.y, m1.y);
            ull NMIg = pk2(-m0.y, -m1.y);
            ull Orr = 0ull, Oii = 0ull;
            for (int j = 0; j < wrp; j++) {
                ull t = fma2(MRg, Orr, fma2(NMIg, Oii, Swr[j][g]));
                Oii   = fma2(MRg, Oii, fma2(MIg, Orr, Swi[j][g]));
                Orr   = t;
            }
            float2 p0 = pw[2 * g], p1 = pw[2 * g + 1];
            ull PRg = pk2(p0.x, p1.x);
            ull PIg = pk2(p0.y, p1.y);
            ull NPIg = pk2(-p0.y, -p1.y);
            ull ir = fma2(PRg, Orr, fma2(NPIg, Oii, SR[g]));
            ull ii = fma2(PRg, Oii, fma2(PIg, Orr, SI[g]));
            ull tr = __shfl_up_sync(0xffffffffu, ir, 1);
            ull ti = __shfl_up_sync(0xffffffffu, ii, 1);
            SR[g] = (lane == 0) ? Orr : tr;
            SI[g] = (lane == 0) ? Oii : ti;
        }
    }

    // ---- phase 3: replay + output dot + D skip + exact GELU (constants reloaded) --
    ull LR[NG], LI[NG], NLI[NG], CR[NG], NCI[NG];
#pragma unroll
    for (int g = 0; g < NG; g++) {
        float2 v0 = g_lam[hh * Nn + 2 * g];
        float2 v1 = g_lam[hh * Nn + 2 * g + 1];
        LR[g]  = pk2(v0.x, v1.x);
        LI[g]  = pk2(v0.y, v1.y);
        NLI[g] = pk2(-v0.y, -v1.y);
        float2 c0 = g_cd2[hh * Nn + 2 * g];
        float2 c1 = g_cd2[hh * Nn + 2 * g + 1];
        CR[g]  = pk2(c0.x, c1.x);
        NCI[g] = pk2(-c0.y, -c1.y);
    }
    float Dh = Dvec[hh];
    uint2* yp = (uint2*)(g_yf16 + (size_t)hh * 16384 + (size_t)b * 4096 + tid * Pc);
#pragma unroll
    for (int q = 0; q < Pc / 4; q++) {
        float4 uv = up[q];
        float xs[4] = {uv.x, uv.y, uv.z, uv.w};
        float ys[4];
#pragma unroll
        for (int e = 0; e < 4; e++) {
            float x = xs[e];
            ull xx = pk2(x, x);
            ull y2 = 0ull;
#pragma unroll
            for (int g = 0; g < NG; g++) {
                ull nr = fma2(LR[g], SR[g], fma2(NLI[g], SI[g], xx));
                ull ni = fma2(LR[g], SI[g], mul2(LI[g], SR[g]));
                SR[g] = nr; SI[g] = ni;
                y2 = fma2(CR[g], nr, y2);
                y2 = fma2(NCI[g], ni, y2);
            }
            float ya, yb;
            upk2(ya, yb, y2);
            float y = fmaf(Dh, x, ya + yb);
            ys[e] = 0.5f * y * (1.0f + erff(y * 0.70710678118654752f));
        }
        __half2 h2a = __floats2half2_rn(ys[0], ys[1]);
        __half2 h2b = __floats2half2_rn(ys[2], ys[3]);
        uint2 pk;
        pk.x = *(uint32_t*)&h2a;
        pk.y = *(uint32_t*)&h2b;
        yp[q] = pk;
    }
}

// ---------------- kernel 3: fp16 1-pass GEMM + GLU + residual (R7-proven loop) -----
#define KC 32
#define ROWA 80
#define ROWB2 528
#define A_REG (128*ROWA)
#define B_REG (KC*ROWB2)
#define STG (A_REG + B_REG)
#define NSTG 4
#define GSMEM (NSTG*STG)

__device__ __forceinline__ void load_stage(uint32_t sbase, int s, int chunk, int by, int bx) {
    int tid = threadIdx.x;
    uint32_t stb = sbase + s * STG;
    {
        int row = tid >> 2, seg = tid & 3;
        int wrow = (row < 64) ? (by * 64 + row) : (1024 + by * 64 + row - 64);
        cp16(stb + (unsigned)row * ROWA + seg * 16,
             g_wf16 + (size_t)wrow * 1024 + chunk * KC + seg * 8);
    }
#pragma unroll
    for (int i = 0; i < 2; i++) {
        int t = i * 512 + tid;
        int row = t >> 5, seg = t & 31;
        cp16(stb + A_REG + (unsigned)row * ROWB2 + seg * 16,
             g_yf16 + (size_t)(chunk * KC + row) * 16384 + bx * 256 + seg * 8);
    }
}

__global__ __launch_bounds__(512, 1) void gemm_glu_kernel(const float* __restrict__ bias,
                                                          const float* __restrict__ hs,
                                                          float* __restrict__ out) {
    extern __shared__ char smem[];
    uint32_t sbase = smem_u32(smem);
    int tid  = threadIdx.x;
    int wid  = tid >> 5;
    int lane = tid & 31;
    int by = blockIdx.x;
    int bx = blockIdx.y;

    int wm = (wid & 1) * 64;
    int wn = (wid >> 1) * 32;
    uint32_t aOff = (uint32_t)(wm + (lane & 15)) * ROWA + (uint32_t)(lane >> 4) * 16;
    uint32_t bOff = (uint32_t)(lane & 15) * ROWB2 + (uint32_t)(lane >> 4) * 16
                  + (uint32_t)wn * 2;

    float acc[64];
#pragma unroll
    for (int i = 0; i < 64; i++) acc[i] = 0.f;

#pragma unroll
    for (int p = 0; p < 3; p++) { load_stage(sbase, p, p, by, bx); cp_commit(); }

    for (int c = 0; c < 32; c++) {
        int s = c & 3;
        cp_wait2();
        __syncthreads();
        if (c + 3 < 32) load_stage(sbase, (c + 3) & 3, c + 3, by, bx);
        cp_commit();
        uint32_t ab = sbase + s * STG;
        uint32_t bb = ab + A_REG;
#pragma unroll
        for (int ks = 0; ks < 2; ks++) {
            uint32_t bf[8], af[16];
            ldsm4t(&bf[0], bb + bOff + (unsigned)ks * (16 * ROWB2));
            ldsm4t(&bf[4], bb + bOff + (unsigned)ks * (16 * ROWB2) + 32);
#pragma unroll
            for (int i = 0; i < 4; i++)
                ldsm4(&af[i * 4], ab + aOff + (unsigned)i * (16 * ROWA) + ks * 32);
#pragma unroll
            for (int i = 0; i < 4; i++)
#pragma unroll
                for (int j = 0; j < 4; j++)
                    mma16816(&acc[(i * 4 + j) * 4], &af[i * 4], &bf[j * 2]);
        }
    }

    float* zsm = (float*)smem;
    int qr = lane >> 2, t4 = lane & 3;
    int n0 = bx * 256, o0 = by * 64;
#pragma unroll
    for (int r = 0; r < 2; r++) {
        __syncthreads();
        if ((wn >> 7) == r) {
            int wnl = wn & 127;
#pragma unroll
            for (int i = 0; i < 4; i++)
#pragma unroll
                for (int j = 0; j < 4; j++) {
                    int m = wm + i * 16 + qr;
                    int n = wnl + j * 8 + t4 * 2;
                    const float* p = &acc[(i * 4 + j) * 4];
                    zsm[n * 132 + m]           = p[0];
                    zsm[(n + 1) * 132 + m]     = p[1];
                    zsm[n * 132 + m + 8]       = p[2];
                    zsm[(n + 1) * 132 + m + 8] = p[3];
                }
        }
        __syncthreads();
#pragma unroll
        for (int it = 0; it < 4; it++) {
            int task = it * 512 + tid;
            int nrow = task >> 4, mg = (task & 15) * 4;
            float4 za = *(const float4*)&zsm[nrow * 132 + mg];
            float4 zg = *(const float4*)&zsm[nrow * 132 + 64 + mg];
            float4 ba = *(const float4*)(bias + o0 + mg);
            float4 bg = *(const float4*)(bias + 1024 + o0 + mg);
            size_t addr = (size_t)(n0 + r * 128 + nrow) * 1024 + o0 + mg;
            float4 hv = *(const float4*)(hs + addr);
            float4 ov;
            ov.x = hv.x + (za.x + ba.x) * (1.0f / (1.0f + expf(-(zg.x + bg.x))));
            ov.y = hv.y + (za.y + ba.y) * (1.0f / (1.0f + expf(-(zg.y + bg.y))));
            ov.z = hv.z + (za.z + ba.z) * (1.0f / (1.0f + expf(-(zg.z + bg.z))));
            ov.w = hv.w + (za.w + ba.w) * (1.0f / (1.0f + expf(-(zg.w + bg.w))));
            *(float4*)(out + addr) = ov;
        }
    }
}

// ---------------- launch ----------------
extern "C" void kernel_launch(void* const* d_in, const int* in_sizes, int n_in,
                              void* d_out, int out_size) {
    const float* hidden     = (const float*)d_in[0];
    const float* attn_mask  = (const float*)d_in[1];
    const float* norm_w     = (const float*)d_in[2];
    const float* log_dt     = (const float*)d_in[3];
    const float* log_A_real = (const float*)d_in[4];
    const float* A_imag     = (const float*)d_in[5];
    const float* C_real     = (const float*)d_in[6];
    const float* C_imag     = (const float*)d_in[7];
    const float* Dvec       = (const float*)d_in[8];
    const float* out_w      = (const float*)d_in[9];
    const float* out_b      = (const float*)d_in[10];
    float* out = (float*)d_out;

    cudaFuncSetAttribute(gemm_glu_kernel, cudaFuncAttributeMaxDynamicSharedMemorySize, GSMEM);
    cudaFuncSetAttribute(norm_fused_kernel, cudaFuncAttributeMaxDynamicSharedMemorySize, NF_SMEM);

    fused_pre_kernel<<<8192 + 64, 256>>>(log_dt, log_A_real, A_imag, C_real, C_imag, out_w);
    norm_fused_kernel<<<dim3(Ll / 32, Bb), 256, NF_SMEM>>>(hidden, attn_mask, norm_w);
    scan_fused_kernel<<<Bb * Hh, 128>>>(Dvec);
    gemm_glu_kernel<<<dim3(16, 64), 512, GSMEM>>>(out_b, hidden, out);
}

// round 11
// speedup vs baseline: 1.5861x; 1.5861x over previous
#include <cuda_runtime.h>
#include <cuda_fp16.h>
#include <math.h>
#include <stdint.h>

// Problem constants
#define Bb 4
#define Ll 4096
#define Hh 1024
#define Nn 16
#define NG 8            // state pairs (f32x2 groups)
#define Pc 32           // elements per scan thread
#define EPSV 1e-6f

typedef unsigned long long ull;

// ---------------- scratch (static device globals; no allocation) ----------------
__device__ float  g_u  [(size_t)Bb*Hh*Ll];   // normalized, masked, (B,H,L)  64MB
__device__ float2 g_lam  [Hh*Nn];
__device__ float2 g_cd2  [Hh*Nn];
__device__ float2 g_lamPk[6 * Hh * Nn];      // lamP^(2^k), k=0..5   (lamP = lam^32)
__device__ float2 g_lamPw[Hh * 32 * Nn];     // lamP^(lane+1)        4MB
__device__ __half g_wf16[2048u*1024u];            // W fp16 [o][k]      4MB
__device__ __half g_yf16[(size_t)1024u*16384u];   // Y fp16 [k=h][n]   32MB

// ================= PTX helpers (legal on base compute_103) =================
__device__ __forceinline__ uint32_t smem_u32(const void* p) {
    uint32_t a;
    asm("{ .reg .u64 t; cvta.to.shared.u64 t, %1; cvt.u32.u64 %0, t; }" : "=r"(a) : "l"(p));
    return a;
}
__device__ __forceinline__ void cp16(uint32_t dst, const void* src) {
    asm volatile("cp.async.cg.shared.global [%0], [%1], 16;" :: "r"(dst), "l"(src));
}
__device__ __forceinline__ void cp_commit() { asm volatile("cp.async.commit_group;"); }
__device__ __forceinline__ void cp_wait2()  { asm volatile("cp.async.wait_group 2;"); }
__device__ __forceinline__ void ldsm4(uint32_t* r, uint32_t addr) {
    asm volatile("ldmatrix.sync.aligned.m8n8.x4.shared.b16 {%0,%1,%2,%3}, [%4];"
                 : "=r"(r[0]), "=r"(r[1]), "=r"(r[2]), "=r"(r[3]) : "r"(addr));
}
__device__ __forceinline__ void ldsm4t(uint32_t* r, uint32_t addr) {
    asm volatile("ldmatrix.sync.aligned.m8n8.x4.trans.shared.b16 {%0,%1,%2,%3}, [%4];"
                 : "=r"(r[0]), "=r"(r[1]), "=r"(r[2]), "=r"(r[3]) : "r"(addr));
}
__device__ __forceinline__ void mma16816(float* d, const uint32_t* a, const uint32_t* b) {
    asm volatile("mma.sync.aligned.m16n8k16.row.col.f32.f16.f16.f32 "
                 "{%0,%1,%2,%3}, {%4,%5,%6,%7}, {%8,%9}, {%0,%1,%2,%3};"
                 : "+f"(d[0]), "+f"(d[1]), "+f"(d[2]), "+f"(d[3])
                 : "r"(a[0]), "r"(a[1]), "r"(a[2]), "r"(a[3]), "r"(b[0]), "r"(b[1]));
}
// ---- packed fp32x2 (Blackwell dual-FMA) ----
__device__ __forceinline__ ull pk2(float a, float b) {
    ull r; asm("mov.b64 %0, {%1,%2};" : "=l"(r) : "f"(a), "f"(b)); return r;
}
__device__ __forceinline__ void upk2(float& a, float& b, ull v) {
    asm("mov.b64 {%0,%1}, %2;" : "=f"(a), "=f"(b) : "l"(v));
}
__device__ __forceinline__ ull fma2(ull a, ull b, ull c) {
    ull d; asm("fma.rn.f32x2 %0, %1, %2, %3;" : "=l"(d) : "l"(a), "l"(b), "l"(c)); return d;
}
__device__ __forceinline__ ull mul2(ull a, ull b) {
    ull d; asm("mul.rn.f32x2 %0, %1, %2;" : "=l"(d) : "l"(a), "l"(b)); return d;
}

// ---------------- kernel 0: constants + power tables (iterative cmul) + W->fp16 ----
__global__ void fused_pre_kernel(const float* __restrict__ log_dt,
                                 const float* __restrict__ log_A_real,
                                 const float* __restrict__ A_imag,
                                 const float* __restrict__ C_real,
                                 const float* __restrict__ C_imag,
                                 const float* __restrict__ wmat) {
    unsigned int bid = blockIdx.x;
    if (bid < 8192u) {
        unsigned int i = bid * 256 + threadIdx.x;
        g_wf16[i] = __float2half_rn(wmat[i]);
        return;
    }
    int idx = (int)(bid - 8192u) * 256 + threadIdx.x;
    if (idx >= Hh * Nn) return;
    int h = idx / Nn;
    int n = idx - h * Nn;
    double dt  = exp((double)log_dt[h]);
    double Are = -exp((double)log_A_real[idx]);
    double Aim = (double)A_imag[idx];
    double dre = Are * dt, dim = Aim * dt;
    double er  = exp(dre);
    double lr  = er * cos(dim), li = er * sin(dim);
    g_lam[idx] = make_float2((float)lr, (float)li);
    // lamP = lam^32 (one transcendental trio)
    double magP = dre * (double)Pc, angP = dim * (double)Pc;
    double erp = exp(magP);
    double pr = erp * cos(angP), pi = erp * sin(angP);
    // lamPk[k] = lamP^(2^k) via iterative squaring
    {
        double qr = pr, qi = pi;
#pragma unroll
        for (int k = 0; k < 6; k++) {
            g_lamPk[k * (Hh * Nn) + idx] = make_float2((float)qr, (float)qi);
            double t = qr * qr - qi * qi;
            qi = 2.0 * qr * qi;
            qr = t;
        }
    }
    // lamPw[j] = lamP^(j+1) via iterative multiply
    {
        double qr = pr, qi = pi;
        for (int j = 0; j < 32; j++) {
            g_lamPw[((size_t)h * 32 + j) * Nn + n] = make_float2((float)qr, (float)qi);
            double t = qr * pr - qi * pi;
            qi = qr * pi + qi * pr;
            qr = t;
        }
    }
    // Cd = C*(lam-1)/A ; store 2*Cd
    double e1r = lr - 1.0, e1i = li;
    double Cr = (double)C_real[idx], Ci = (double)C_imag[idx];
    double nr = Cr * e1r - Ci * e1i;
    double ni = Cr * e1i + Ci * e1r;
    double den = Are * Are + Aim * Aim;
    double cdr = (nr * Are + ni * Aim) / den;
    double cdi = (ni * Are - nr * Aim) / den;
    g_cd2[idx] = make_float2((float)(2.0 * cdr), (float)(2.0 * cdi));
}

// ---------------- kernel 1: fused RMSNorm + mask + transpose ----------------
#define NF_TILE  (32 * 1025)
#define NF_SMEM  ((NF_TILE + 32 + 1024) * 4)
__global__ __launch_bounds__(256) void norm_fused_kernel(const float* __restrict__ hs,
                                                         const float* __restrict__ mask,
                                                         const float* __restrict__ w) {
    extern __shared__ float sm[];
    float* tile = sm;
    float* rm   = sm + NF_TILE;
    float* w_s  = sm + NF_TILE + 32;
    int b  = blockIdx.y;
    int l0 = blockIdx.x * 32;
    int tid = threadIdx.x;
    int row = tid >> 3;
    int sub = tid & 7;

    for (int i = tid; i < 1024; i += 256) w_s[i] = w[i];

    const float4* src = (const float4*)(hs + ((size_t)(b * Ll + l0 + row)) * Hh);
    float ss = 0.f;
#pragma unroll
    for (int i = 0; i < 32; i++) {
        int col4 = i * 8 + sub;
        float4 v = src[col4];
        ss += v.x * v.x + v.y * v.y + v.z * v.z + v.w * v.w;
        float* dst = &tile[row * 1025 + col4 * 4];
        dst[0] = v.x; dst[1] = v.y; dst[2] = v.z; dst[3] = v.w;
    }
#pragma unroll
    for (int o = 4; o; o >>= 1) ss += __shfl_xor_sync(0xffffffffu, ss, o);
    if (sub == 0)
        rm[row] = rsqrtf(ss * (1.0f / Hh) + EPSV) * mask[b * Ll + l0 + row];
    __syncthreads();

#pragma unroll 8
    for (int i = 0; i < 128; i++) {
        int lin = i * 256 + tid;
        int h = lin >> 5, l = lin & 31;
        g_u[((size_t)(b * Hh + h)) * Ll + l0 + l] = tile[l * 1025 + h] * rm[l] * w_s[h];
    }
}

// ---------------- kernel 2: FUSED scan, f32x2, table-driven (low reg pressure) -----
__global__ __launch_bounds__(128) void scan_fused_kernel(const float* __restrict__ Dvec) {
    int bh  = blockIdx.x;
    int hh  = bh & (Hh - 1);
    int b   = bh >> 10;
    int tid = threadIdx.x;
    int lane = tid & 31, wrp = tid >> 5;

    ull SR[NG], SI[NG];
#pragma unroll
    for (int g = 0; g < NG; g++) { SR[g] = 0ull; SI[g] = 0ull; }

    const float4* up = (const float4*)(g_u + (size_t)bh * Ll + tid * Pc);

    // ---- phase 1: local scan of 32 elements (lam constants scoped/dead after) ----
    {
        ull LR[NG], LI[NG], NLI[NG];
#pragma unroll
        for (int g = 0; g < NG; g++) {
            float2 v0 = g_lam[hh * Nn + 2 * g];
            float2 v1 = g_lam[hh * Nn + 2 * g + 1];
            LR[g]  = pk2(v0.x, v1.x);
            LI[g]  = pk2(v0.y, v1.y);
            NLI[g] = pk2(-v0.y, -v1.y);
        }
#pragma unroll
        for (int q = 0; q < Pc / 4; q++) {
            float4 uv = up[q];
            float xs[4] = {uv.x, uv.y, uv.z, uv.w};
#pragma unroll
            for (int e = 0; e < 4; e++) {
                ull xx = pk2(xs[e], xs[e]);
#pragma unroll
                for (int g = 0; g < NG; g++) {
                    ull nr = fma2(LR[g], SR[g], fma2(NLI[g], SI[g], xx));
                    ull ni = fma2(LR[g], SI[g], mul2(LI[g], SR[g]));
                    SR[g] = nr; SI[g] = ni;
                }
            }
        }
    }

    // ---- phase 2: Kogge-Stone over 32 lanes; step multipliers from table ----
#pragma unroll
    for (int k = 0; k < 5; k++) {
        int off = 1 << k;
        const float2* mk = g_lamPk + k * (Hh * Nn) + hh * Nn;
#pragma unroll
        for (int g = 0; g < NG; g++) {
            float2 m0 = mk[2 * g], m1 = mk[2 * g + 1];
            ull MRg = pk2(m0.x, m1.x);
            ull MIg = pk2(m0.y, m1.y);
            ull NMIg = pk2(-m0.y, -m1.y);
            ull vr = __shfl_up_sync(0xffffffffu, SR[g], off);
            ull vi = __shfl_up_sync(0xffffffffu, SI[g], off);
            ull nsr = fma2(MRg, vr, fma2(NMIg, vi, SR[g]));
            ull nsi = fma2(MRg, vi, fma2(MIg, vr, SI[g]));
            if (lane >= off) { SR[g] = nsr; SI[g] = nsi; }
        }
    }

    // cross-warp combine with M32 = lamP^32
    __shared__ ull Swr[4][NG], Swi[4][NG];
    if (lane == 31) {
#pragma unroll
        for (int g = 0; g < NG; g++) { Swr[wrp][g] = SR[g]; Swi[wrp][g] = SI[g]; }
    }
    __syncthreads();
    {
        const float2* mk = g_lamPk + 5 * (Hh * Nn) + hh * Nn;
        const float2* pw = g_lamPw + ((size_t)hh * 32 + lane) * Nn;
#pragma unroll
        for (int g = 0; g < NG; g++) {
            float2 m0 = mk[2 * g], m1 = mk[2 * g + 1];
            ull MRg = pk2(m0.x, m1.x);
            ull MIg = pk2(m0.y, m1.y);
            ull NMIg = pk2(-m0.y, -m1.y);
            ull Orr = 0ull, Oii = 0ull;
            for (int j = 0; j < wrp; j++) {
                ull t = fma2(MRg, Orr, fma2(NMIg, Oii, Swr[j][g]));
                Oii   = fma2(MRg, Oii, fma2(MIg, Orr, Swi[j][g]));
                Orr   = t;
            }
            float2 p0 = pw[2 * g], p1 = pw[2 * g + 1];
            ull PRg = pk2(p0.x, p1.x);
            ull PIg = pk2(p0.y, p1.y);
            ull NPIg = pk2(-p0.y, -p1.y);
            ull ir = fma2(PRg, Orr, fma2(NPIg, Oii, SR[g]));
            ull ii = fma2(PRg, Oii, fma2(PIg, Orr, SI[g]));
            ull tr = __shfl_up_sync(0xffffffffu, ir, 1);
            ull ti = __shfl_up_sync(0xffffffffu, ii, 1);
            SR[g] = (lane == 0) ? Orr : tr;
            SI[g] = (lane == 0) ? Oii : ti;
        }
    }

    // ---- phase 3: replay + output dot + D skip + exact GELU (constants reloaded) --
    ull LR[NG], LI[NG], NLI[NG], CR[NG], NCI[NG];
#pragma unroll
    for (int g = 0; g < NG; g++) {
        float2 v0 = g_lam[hh * Nn + 2 * g];
        float2 v1 = g_lam[hh * Nn + 2 * g + 1];
        LR[g]  = pk2(v0.x, v1.x);
        LI[g]  = pk2(v0.y, v1.y);
        NLI[g] = pk2(-v0.y, -v1.y);
        float2 c0 = g_cd2[hh * Nn + 2 * g];
        float2 c1 = g_cd2[hh * Nn + 2 * g + 1];
        CR[g]  = pk2(c0.x, c1.x);
        NCI[g] = pk2(-c0.y, -c1.y);
    }
    float Dh = Dvec[hh];
    uint2* yp = (uint2*)(g_yf16 + (size_t)hh * 16384 + (size_t)b * 4096 + tid * Pc);
#pragma unroll
    for (int q = 0; q < Pc / 4; q++) {
        float4 uv = up[q];
        float xs[4] = {uv.x, uv.y, uv.z, uv.w};
        float ys[4];
#pragma unroll
        for (int e = 0; e < 4; e++) {
            float x = xs[e];
            ull xx = pk2(x, x);
            ull y2 = 0ull;
#pragma unroll
            for (int g = 0; g < NG; g++) {
                ull nr = fma2(LR[g], SR[g], fma2(NLI[g], SI[g], xx));
                ull ni = fma2(LR[g], SI[g], mul2(LI[g], SR[g]));
                SR[g] = nr; SI[g] = ni;
                y2 = fma2(CR[g], nr, y2);
                y2 = fma2(NCI[g], ni, y2);
            }
            float ya, yb;
            upk2(ya, yb, y2);
            float y = fmaf(Dh, x, ya + yb);
            ys[e] = 0.5f * y * (1.0f + erff(y * 0.70710678118654752f));
        }
        __half2 h2a = __floats2half2_rn(ys[0], ys[1]);
        __half2 h2b = __floats2half2_rn(ys[2], ys[3]);
        uint2 pk;
        pk.x = *(uint32_t*)&h2a;
        pk.y = *(uint32_t*)&h2b;
        yp[q] = pk;
    }
}

// ---------------- kernel 3: fp16 1-pass GEMM + GLU + residual (R7-proven loop) -----
#define KC 32
#define ROWA 80
#define ROWB2 528
#define A_REG (128*ROWA)
#define B_REG (KC*ROWB2)
#define STG (A_REG + B_REG)
#define NSTG 4
#define GSMEM (NSTG*STG)

__device__ __forceinline__ void load_stage(uint32_t sbase, int s, int chunk, int by, int bx) {
    int tid = threadIdx.x;
    uint32_t stb = sbase + s * STG;
    {
        int row = tid >> 2, seg = tid & 3;
        int wrow = (row < 64) ? (by * 64 + row) : (1024 + by * 64 + row - 64);
        cp16(stb + (unsigned)row * ROWA + seg * 16,
             g_wf16 + (size_t)wrow * 1024 + chunk * KC + seg * 8);
    }
#pragma unroll
    for (int i = 0; i < 2; i++) {
        int t = i * 512 + tid;
        int row = t >> 5, seg = t & 31;
        cp16(stb + A_REG + (unsigned)row * ROWB2 + seg * 16,
             g_yf16 + (size_t)(chunk * KC + row) * 16384 + bx * 256 + seg * 8);
    }
}

__global__ __launch_bounds__(512, 1) void gemm_glu_kernel(const float* __restrict__ bias,
                                                          const float* __restrict__ hs,
                                                          float* __restrict__ out) {
    extern __shared__ char smem[];
    uint32_t sbase = smem_u32(smem);
    int tid  = threadIdx.x;
    int wid  = tid >> 5;
    int lane = tid & 31;
    int by = blockIdx.x;
    int bx = blockIdx.y;

    int wm = (wid & 1) * 64;
    int wn = (wid >> 1) * 32;
    uint32_t aOff = (uint32_t)(wm + (lane & 15)) * ROWA + (uint32_t)(lane >> 4) * 16;
    uint32_t bOff = (uint32_t)(lane & 15) * ROWB2 + (uint32_t)(lane >> 4) * 16
                  + (uint32_t)wn * 2;

    float acc[64];
#pragma unroll
    for (int i = 0; i < 64; i++) acc[i] = 0.f;

#pragma unroll
    for (int p = 0; p < 3; p++) { load_stage(sbase, p, p, by, bx); cp_commit(); }

    for (int c = 0; c < 32; c++) {
        int s = c & 3;
        cp_wait2();
        __syncthreads();
        if (c + 3 < 32) load_stage(sbase, (c + 3) & 3, c + 3, by, bx);
        cp_commit();
        uint32_t ab = sbase + s * STG;
        uint32_t bb = ab + A_REG;
#pragma unroll
        for (int ks = 0; ks < 2; ks++) {
            uint32_t bf[8], af[16];
            ldsm4t(&bf[0], bb + bOff + (unsigned)ks * (16 * ROWB2));
            ldsm4t(&bf[4], bb + bOff + (unsigned)ks * (16 * ROWB2) + 32);
#pragma unroll
            for (int i = 0; i < 4; i++)
                ldsm4(&af[i * 4], ab + aOff + (unsigned)i * (16 * ROWA) + ks * 32);
#pragma unroll
            for (int i = 0; i < 4; i++)
#pragma unroll
                for (int j = 0; j < 4; j++)
                    mma16816(&acc[(i * 4 + j) * 4], &af[i * 4], &bf[j * 2]);
        }
    }

    float* zsm = (float*)smem;
    int qr = lane >> 2, t4 = lane & 3;
    int n0 = bx * 256, o0 = by * 64;
#pragma unroll
    for (int r = 0; r < 2; r++) {
        __syncthreads();
        if ((wn >> 7) == r) {
            int wnl = wn & 127;
#pragma unroll
            for (int i = 0; i < 4; i++)
#pragma unroll
                for (int j = 0; j < 4; j++) {
                    int m = wm + i * 16 + qr;
                    int n = wnl + j * 8 + t4 * 2;
                    const float* p = &acc[(i * 4 + j) * 4];
                    zsm[n * 132 + m]           = p[0];
                    zsm[(n + 1) * 132 + m]     = p[1];
                    zsm[n * 132 + m + 8]       = p[2];
                    zsm[(n + 1) * 132 + m + 8] = p[3];
                }
        }
        __syncthreads();
#pragma unroll
        for (int it = 0; it < 4; it++) {
            int task = it * 512 + tid;
            int nrow = task >> 4, mg = (task & 15) * 4;
            float4 za = *(const float4*)&zsm[nrow * 132 + mg];
            float4 zg = *(const float4*)&zsm[nrow * 132 + 64 + mg];
            float4 ba = *(const float4*)(bias + o0 + mg);
            float4 bg = *(const float4*)(bias + 1024 + o0 + mg);
            size_t addr = (size_t)(n0 + r * 128 + nrow) * 1024 + o0 + mg;
            float4 hv = *(const float4*)(hs + addr);
            float4 ov;
            ov.x = hv.x + (za.x + ba.x) * (1.0f / (1.0f + expf(-(zg.x + bg.x))));
            ov.y = hv.y + (za.y + ba.y) * (1.0f / (1.0f + expf(-(zg.y + bg.y))));
            ov.z = hv.z + (za.z + ba.z) * (1.0f / (1.0f + expf(-(zg.z + bg.z))));
            ov.w = hv.w + (za.w + ba.w) * (1.0f / (1.0f + expf(-(zg.w + bg.w))));
            *(float4*)(out + addr) = ov;
        }
    }
}

// ---------------- launch ----------------
extern "C" void kernel_launch(void* const* d_in, const int* in_sizes, int n_in,
                              void* d_out, int out_size) {
    const float* hidden     = (const float*)d_in[0];
    const float* attn_mask  = (const float*)d_in[1];
    const float* norm_w     = (const float*)d_in[2];
    const float* log_dt     = (const float*)d_in[3];
    const float* log_A_real = (const float*)d_in[4];
    const float* A_imag     = (const float*)d_in[5];
    const float* C_real     = (const float*)d_in[6];
    const float* C_imag     = (const float*)d_in[7];
    const float* Dvec       = (const float*)d_in[8];
    const float* out_w      = (const float*)d_in[9];
    const float* out_b      = (const float*)d_in[10];
    float* out = (float*)d_out;

    cudaFuncSetAttribute(gemm_glu_kernel, cudaFuncAttributeMaxDynamicSharedMemorySize, GSMEM);
    cudaFuncSetAttribute(norm_fused_kernel, cudaFuncAttributeMaxDynamicSharedMemorySize, NF_SMEM);

    fused_pre_kernel<<<8192 + 64, 256>>>(log_dt, log_A_real, A_imag, C_real, C_imag, out_w);
    norm_fused_kernel<<<dim3(Ll / 32, Bb), 256, NF_SMEM>>>(hidden, attn_mask, norm_w);
    scan_fused_kernel<<<Bb * Hh, 128>>>(Dvec);
    gemm_glu_kernel<<<dim3(16, 64), 512, GSMEM>>>(out_b, hidden, out);
}